// round 4
// baseline (speedup 1.0000x reference)
#include <cuda_runtime.h>
#include <cuda_bf16.h>

#define LOOP 100
#define BN_EPS 1e-5f

__device__ __forceinline__ float ex2_approx(float x) {
    float y; asm("ex2.approx.f32 %0, %1;" : "=f"(y) : "f"(x)); return y;
}
__device__ __forceinline__ float rcp_approx(float x) {
    float y; asm("rcp.approx.f32 %0, %1;" : "=f"(y) : "f"(x)); return y;
}
__device__ __forceinline__ float tanh_approx(float x) {
    float y; asm("tanh.approx.f32 %0, %1;" : "=f"(y) : "f"(x)); return y;
}
__device__ __forceinline__ float sqrt_approx(float x) {
    float y; asm("sqrt.approx.f32 %0, %1;" : "=f"(y) : "f"(x)); return y;
}
__device__ __forceinline__ float fast_sigmoid(float a) {
    return rcp_approx(1.0f + ex2_approx(-a * 1.4426950408889634f));
}

__global__ void __launch_bounds__(256, 1)
model_fused_kernel(const float* __restrict__ x,
                   const float* __restrict__ conv_w,
                   const float* __restrict__ conv_b,
                   const float* __restrict__ bn_gamma,
                   const float* __restrict__ bn_beta,
                   const float* __restrict__ bn_mean,
                   const float* __restrict__ bn_var,
                   const float* __restrict__ w1,
                   const float* __restrict__ b1,
                   const float* __restrict__ w2,
                   const float* __restrict__ b2,
                   const float* __restrict__ w3,
                   const float* __restrict__ b3,
                   float* __restrict__ out)
{
    // kk: flat history kk[t*16+p]; feats[i][j] = kk[i*100+j]
    __shared__ __align__(16) float kk[LOOP * 16];
    __shared__ __align__(16) float w1s[60 * 100];
    __shared__ __align__(16) float w2s[16 * 60];
    __shared__ __align__(16) float w3s[8 * 16];
    __shared__ __align__(16) float h1n[16 * 60];
    __shared__ __align__(16) float h2s[16 * 16];
    __shared__ float b1s[60];
    __shared__ float b2s[16];
    __shared__ float b3s[8];
    __shared__ int prog;

    const int tid = threadIdx.x;

    if (tid == 0) prog = 0;
    __syncthreads();

    if (tid < 16) {
        // ======== Phase 1: serial conv recurrence (warp 0, lanes 0-15) ========
        const int r = tid >> 2;
        const int c = tid & 3;

        // Halved, boundary-masked weights -> recurrence computes a' = a/2
        float wm[9];
        int   ln[9];
        #pragma unroll
        for (int dr = 0; dr < 3; dr++) {
            #pragma unroll
            for (int dc = 0; dc < 3; dc++) {
                const int nr = r + dr - 1;
                const int nc = c + dc - 1;
                const bool ok = ((unsigned)nr < 4u) && ((unsigned)nc < 4u);
                const int k = dr * 3 + dc;
                wm[k] = ok ? 0.5f * conv_w[k] : 0.0f;
                ln[k] = ok ? (nr * 4 + nc) : tid;
            }
        }
        const float cbh     = 0.5f * conv_b[0];
        const float inv_std = bn_gamma[0] * rsqrtf(bn_var[0] + BN_EPS);
        const float shift   = bn_beta[0] - bn_mean[0] * inv_std;
        const float c1      = 2.0f * inv_std;   // p2 = 0.5*inv_std*a^2 = 2*inv_std*a'^2
        const float sh2     = 2.0f * shift;     // a*shift = 2*shift*a'

        float v = x[tid];

        #pragma unroll
        for (int chunk = 0; chunk < 4; chunk++) {
            #pragma unroll 5
            for (int tt = 0; tt < 25; tt++) {
                const int t = chunk * 25 + tt;
                // 8 neighbor shuffles; center term q overlaps the shfl latency
                const float n0 = __shfl_sync(0x0000FFFFu, v, ln[0]);
                const float n1 = __shfl_sync(0x0000FFFFu, v, ln[1]);
                const float n2 = __shfl_sync(0x0000FFFFu, v, ln[2]);
                const float n3 = __shfl_sync(0x0000FFFFu, v, ln[3]);
                const float n5 = __shfl_sync(0x0000FFFFu, v, ln[5]);
                const float n6 = __shfl_sync(0x0000FFFFu, v, ln[6]);
                const float n7 = __shfl_sync(0x0000FFFFu, v, ln[7]);
                const float n8 = __shfl_sync(0x0000FFFFu, v, ln[8]);

                const float q  = fmaf(wm[4], v, cbh);
                float p0 = fmaf(wm[0], n0, q);
                p0       = fmaf(wm[7], n7, p0);
                const float p1 = fmaf(wm[2], n2, wm[1] * n1);
                const float p2 = fmaf(wm[5], n5, wm[3] * n3);
                const float p3 = fmaf(wm[8], n8, wm[6] * n6);
                const float ap = (p0 + p1) + (p2 + p3);   // a' = a/2, depth 16

                // h = p*tanh(a') + (p + 2*shift*a'),  p = 2*inv_std*a'^2
                const float th = tanh_approx(ap);
                const float t1 = ap * c1;
                const float p  = ap * t1;
                const float pq = fmaf(ap, sh2, p);
                const float h  = fmaf(p, th, pq);

                // xn = sign(h)*sqrt(|h|); |h| folds into MUFU operand modifier
                const float xn = copysignf(sqrt_approx(fabsf(h)), h);

                kk[t * 16 + tid] = xn;
                v = xn;
            }
            if (chunk < 3 && tid == 0) {
                __threadfence_block();                 // release kk stores
                *(volatile int*)&prog = chunk + 1;
            }
        }
    } else if (tid >= 32) {
        // ======== Warps 1-7: prefetch weights, then consume kk chunks =========
        const int pt = tid - 32;             // 0..223
        const int NP = 224;
        for (int i = pt; i < 6000; i += NP) w1s[i] = w1[i];
        for (int i = pt; i < 960;  i += NP) w2s[i] = w2[i];
        for (int i = pt; i < 128;  i += NP) w3s[i] = w3[i];
        for (int i = pt; i < 60;   i += NP) b1s[i] = b1[i];
        if (pt < 16) b2s[pt] = b2[pt];
        if (pt < 8)  b3s[pt] = b3[pt];

        // all consumer prefetches must land before any consumer reads w1s
        asm volatile("bar.sync 1, 224;" ::: "memory");

        // chunks 0..2 overlapped with phase 1 (rows 4c..4c+3 ready at t=25(c+1))
        for (int cchunk = 0; cchunk < 3; cchunk++) {
            while (*(volatile const int*)&prog < cchunk + 1) __nanosleep(40);
            __threadfence_block();                    // acquire kk stores
            for (int task = pt; task < 240; task += NP) {
                const int i = cchunk * 4 + task / 60;
                const int o = task % 60;
                const float4* f4 = (const float4*)&kk[i * 100];
                const float4* g4 = (const float4*)&w1s[o * 100];
                float a0 = 0.f, a1 = 0.f, a2 = 0.f, a3 = 0.f;
                #pragma unroll
                for (int j = 0; j < 25; j++) {
                    const float4 f = f4[j];
                    const float4 g = g4[j];
                    a0 = fmaf(f.x, g.x, a0);
                    a1 = fmaf(f.y, g.y, a1);
                    a2 = fmaf(f.z, g.z, a2);
                    a3 = fmaf(f.w, g.w, a3);
                }
                const float hv = (a0 + a1) + (a2 + a3) + b1s[o];
                const float sw = hv * fast_sigmoid(hv);
                h1n[i * 60 + o] = 2.0f * sw - 1.0f;
            }
        }
    }
    __syncthreads();

    // ======== Chunk 3 of phase 2 (rows 12-15), all 256 threads =============
    if (tid < 240) {
        const int i = 12 + tid / 60;
        const int o = tid % 60;
        const float4* f4 = (const float4*)&kk[i * 100];
        const float4* g4 = (const float4*)&w1s[o * 100];
        float a0 = 0.f, a1 = 0.f, a2 = 0.f, a3 = 0.f;
        #pragma unroll
        for (int j = 0; j < 25; j++) {
            const float4 f = f4[j];
            const float4 g = g4[j];
            a0 = fmaf(f.x, g.x, a0);
            a1 = fmaf(f.y, g.y, a1);
            a2 = fmaf(f.z, g.z, a2);
            a3 = fmaf(f.w, g.w, a3);
        }
        const float hv = (a0 + a1) + (a2 + a3) + b1s[o];
        const float sw = hv * fast_sigmoid(hv);
        h1n[i * 60 + o] = 2.0f * sw - 1.0f;
    }
    __syncthreads();

    const int warp = tid >> 5;
    const int lane = tid & 31;
    const int i    = lane & 15;
    const int sub  = lane >> 4;

    // ======== Phase 3: h2 = swish(h1n @ w2.T + b2), 16x16 ==================
    {
        const int o = 2 * warp + sub;                // 0..15
        const float4* f4 = (const float4*)&h1n[i * 60];
        const float4* g4 = (const float4*)&w2s[o * 60];
        float a0 = 0.f, a1 = 0.f, a2 = 0.f, a3 = 0.f;
        #pragma unroll
        for (int j = 0; j < 15; j++) {
            const float4 f = f4[j];
            const float4 g = g4[j];
            a0 = fmaf(f.x, g.x, a0);
            a1 = fmaf(f.y, g.y, a1);
            a2 = fmaf(f.z, g.z, a2);
            a3 = fmaf(f.w, g.w, a3);
        }
        const float hv = (a0 + a1) + (a2 + a3) + b2s[o];
        h2s[i * 16 + o] = hv * fast_sigmoid(hv);
    }
    __syncthreads();

    // ======== Phase 4: y = h2 @ w3.T + b3 (128 outputs) ====================
    if (tid < 128) {
        const int ii = tid >> 3;
        const int o  = tid & 7;
        const float4* f4 = (const float4*)&h2s[ii * 16];
        const float4* g4 = (const float4*)&w3s[o * 16];
        float acc = 0.f;
        #pragma unroll
        for (int j = 0; j < 4; j++) {
            const float4 f = f4[j];
            const float4 g = g4[j];
            acc = fmaf(f.x, g.x, acc);
            acc = fmaf(f.y, g.y, acc);
            acc = fmaf(f.z, g.z, acc);
            acc = fmaf(f.w, g.w, acc);
        }
        out[tid] = acc + b3s[o];
    }
}

extern "C" void kernel_launch(void* const* d_in, const int* in_sizes, int n_in,
                              void* d_out, int out_size)
{
    const float* x        = (const float*)d_in[0];
    const float* conv_w   = (const float*)d_in[1];
    const float* conv_b   = (const float*)d_in[2];
    const float* bn_gamma = (const float*)d_in[3];
    const float* bn_beta  = (const float*)d_in[4];
    const float* bn_mean  = (const float*)d_in[5];
    const float* bn_var   = (const float*)d_in[6];
    const float* w1       = (const float*)d_in[7];
    const float* b1       = (const float*)d_in[8];
    const float* w2       = (const float*)d_in[9];
    const float* b2       = (const float*)d_in[10];
    const float* w3       = (const float*)d_in[11];
    const float* b3       = (const float*)d_in[12];
    float* out = (float*)d_out;

    model_fused_kernel<<<1, 256>>>(x, conv_w, conv_b, bn_gamma, bn_beta,
                                   bn_mean, bn_var, w1, b1, w2, b2, w3, b3, out);
}